// round 12
// baseline (speedup 1.0000x reference)
#include <cuda_runtime.h>
#include <cuda_fp16.h>
#include <mma.h>
#include <math.h>

using namespace nvcuda;

#define N_NODES 50000
#define N_EDGES 1600000
#define D 128
#define NET 8
#define K_HOPS 10

#define CB ((N_NODES * D / 4 + 255) / 256)  // cvt blocks

// ---- static scratch ----
__device__ __half g_h16A[N_NODES * D];
__device__ __half g_h16B[N_NODES * D];
__device__ __half g_f016[N_NODES * D];   // fp16(feat) for residual
__device__ int   g_meta[N_EDGES + 64];   // src | (etype<<16), CSR-ordered by dst
__device__ int   g_ptr[N_NODES + 1];
__device__ int   g_order[N_NODES];       // node ids, degree-descending
__device__ int   g_indeg[N_NODES];
__device__ int   g_outdeg[N_NODES];
__device__ int   g_fill[N_NODES];
__device__ float g_srcnorm[N_NODES];
__device__ float2 g_abZ[N_NODES];        // {0.9*dn*sn, 0.1*sn}  -> writes z = h*sn
__device__ float2 g_abH[N_NODES];        // {0.9*dn,    0.1   }  -> writes h (last hop)
__device__ float g_gate[NET];            // 1 + sigmoid(MLP(embed[t]))
__device__ __half g_W1h[D * D];          // fp16 copies of MLP weights
__device__ __half g_W2h[D * D];

__device__ __forceinline__ float gelu_exact(float x) {
    return 0.5f * x * (1.0f + erff(x * 0.70710678118654752440f));
}

// ---------------- launch 0: zero counters ----------------
__global__ void k_zero() {
    int i = blockIdx.x * blockDim.x + threadIdx.x;
    if (i < N_NODES) { g_indeg[i] = 0; g_outdeg[i] = 0; g_fill[i] = 0; }
}

// ---------------- launch 1: degree count ----------------
__global__ void k_deg(const int* __restrict__ src, const int* __restrict__ dst) {
    int e = blockIdx.x * blockDim.x + threadIdx.x;
    if (e < N_EDGES) {
        atomicAdd(&g_outdeg[src[e]], 1);
        atomicAdd(&g_indeg[dst[e]], 1);
    }
}

// ------ launch 2: CSR ptr scan + norms + degree-descending order (single block) ------
__global__ void k_scan() {
    __shared__ int sm[1024];
    __shared__ int hist[1024];   // capped-degree histogram -> then per-bin cursors
    __shared__ int hs[1024];     // scratch for descending prefix
    int t = threadIdx.x;
    hist[t] = 0;
    __syncthreads();

    const int CH = (N_NODES + 1023) / 1024;   // 49
    int beg = t * CH, end = min(beg + CH, N_NODES);
    int s = 0;
    for (int i = beg; i < end; i++) {
        int id = g_indeg[i];
        s += id;
        float sn = rsqrtf(fmaxf((float)g_outdeg[i], 1.0f));
        float dn = rsqrtf(fmaxf((float)id, 1.0f));
        g_srcnorm[i] = sn;
        g_abZ[i] = make_float2(0.9f * dn * sn, 0.1f * sn);
        g_abH[i] = make_float2(0.9f * dn, 0.1f);
        atomicAdd(&hist[min(id, 1023)], 1);
    }
    sm[t] = s;
    __syncthreads();
    for (int d = 1; d < 1024; d <<= 1) {
        int add = (t >= d) ? sm[t - d] : 0;
        __syncthreads();
        sm[t] += add;
        __syncthreads();
    }
    int off = sm[t] - s;
    for (int i = beg; i < end; i++) { g_ptr[i] = off; off += g_indeg[i]; }
    if (t == 1023) g_ptr[N_NODES] = off;

    // descending-degree exclusive prefix of the histogram.
    // rank r = 1023 - t corresponds to degree bin (1023 - r) ... use hs over reversed idx.
    int hv = hist[1023 - t];     // value at descending rank t
    hs[t] = hv;
    __syncthreads();
    for (int d = 1; d < 1024; d <<= 1) {
        int add = (t >= d) ? hs[t - d] : 0;
        __syncthreads();
        hs[t] += add;
        __syncthreads();
    }
    hist[1023 - t] = hs[t] - hv;   // start cursor for bin (1023-t), descending order
    __syncthreads();
    // scatter node ids into g_order (within-bin order arbitrary)
    for (int i = beg; i < end; i++) {
        int b = min(g_indeg[i], 1023);
        int pos = atomicAdd(&hist[b], 1);
        g_order[pos] = i;
    }
}

// ---------------- launch 3 (PROFILED SLOT): bucket edges by dst ----------------
__global__ void k_scatter(const int* __restrict__ src, const int* __restrict__ dst,
                          const int* __restrict__ ef) {
    int e = blockIdx.x * blockDim.x + threadIdx.x;
    if (e < N_EDGES) {
        int d = dst[e];
        int pos = g_ptr[d] + atomicAdd(&g_fill[d], 1);
        g_meta[pos] = src[e] | (ef[e] << 16);   // src < 65536, etype < 8
    }
}

// ------- launch 4: z0/f016 converts + W1/W2 -> fp16 + edge gate, one fused grid -------
__global__ void k_cvtgate(const float* __restrict__ feat,
                          const float* __restrict__ W1, const float* __restrict__ W2,
                          const float* __restrict__ emb, const float* __restrict__ We1,
                          const float* __restrict__ be1, const float* __restrict__ We2,
                          const float* __restrict__ be2) {
    int b = blockIdx.x, tid = threadIdx.x;
    if (b < CB) {
        int i = b * 256 + tid;
        if (i < N_NODES * D / 4) {
            int row = i >> 5;                       // (i*4)/128
            float sn = g_srcnorm[row];
            float4 v = *(const float4*)(feat + i * 4);
            __half2 a = __floats2half2_rn(v.x, v.y);
            __half2 c = __floats2half2_rn(v.z, v.w);
            uint2 u;  u.x = *(unsigned int*)&a;  u.y = *(unsigned int*)&c;
            *(uint2*)(g_f016 + i * 4) = u;
            __half2 za = __floats2half2_rn(v.x * sn, v.y * sn);
            __half2 zc = __floats2half2_rn(v.z * sn, v.w * sn);
            uint2 zu; zu.x = *(unsigned int*)&za; zu.y = *(unsigned int*)&zc;
            *(uint2*)(g_h16A + i * 4) = zu;         // z0 lives in buffer A
        }
    } else if (b < CB + 64) {
        int i = (b - CB) * 256 + tid;               // 64*256 = 16384 = D*D
        g_W1h[i] = __float2half_rn(W1[i]);
    } else if (b < CB + 128) {
        int i = (b - CB - 64) * 256 + tid;
        g_W2h[i] = __float2half_rn(W2[i]);
    } else {
        int w = tid >> 5, lane = tid & 31;
        if (w < NET) {
            float acc = be1[lane];
            #pragma unroll 8
            for (int i = 0; i < D; i++)
                acc = fmaf(emb[w * D + i], We1[i * 32 + lane], acc);
            float g = gelu_exact(acc);
            float v = g * We2[lane];
            #pragma unroll
            for (int o = 16; o; o >>= 1) v += __shfl_down_sync(0xffffffffu, v, o);
            if (lane == 0)
                g_gate[w] = 1.0f + 1.0f / (1.0f + expf(-(v + be2[0])));
        }
    }
}

// ---------------- hop: warp per dst node (degree-desc order), f32x2 FMA ----------------
__device__ __forceinline__ void accp2(unsigned long long* a, float cbc, uint4 u) {
    unsigned long long c2;
    asm("mov.b64 %0, {%1, %1};" : "=l"(c2) : "f"(cbc));
    __half2* hp = (__half2*)&u;
    #pragma unroll
    for (int q = 0; q < 4; q++) {
        float2 f = __half22float2(hp[q]);
        unsigned long long v;
        asm("mov.b64 %0, {%1, %2};" : "=l"(v) : "f"(f.x), "f"(f.y));
        asm("fma.rn.f32x2 %0, %1, %2, %0;" : "+l"(a[q]) : "l"(v), "l"(c2));
    }
}

__global__ void __launch_bounds__(256, 5) k_hop(const __half* __restrict__ z_in,
                                                __half* __restrict__ h_out,
                                                const float2* __restrict__ ab) {
    int gw0  = (blockIdx.x * blockDim.x + threadIdx.x) >> 5;
    int lane = threadIdx.x & 31;
    if (gw0 >= N_NODES) return;
    int gw = g_order[gw0];                        // heavy nodes scheduled first
    int beg = g_ptr[gw], end = g_ptr[gw + 1];
    int half = lane >> 4;
    int col  = (lane & 15) * 8;                   // 8 halves (16 B) per lane
    float gate_reg = g_gate[lane & 7];            // 8 gate values resident in warp

    unsigned long long acc[4] = {0ull, 0ull, 0ull, 0ull};

    for (int e0 = beg; e0 < end; e0 += 32) {
        int m = min(32, end - e0);
        int mv = (lane < m) ? g_meta[e0 + lane] : 0;
        int ssrc = mv & 0xffff;
        float gv = __shfl_sync(0xffffffffu, gate_reg, (mv >> 16) & 7);
        float cl = (lane < m) ? gv : 0.0f;        // inactive lanes contribute 0
        int i = 0;
        for (; i + 8 <= m; i += 8) {              // 4 pairs = 8 edges, 4 LDG.128 in flight
            int i0 = i + half, i1 = i + 2 + half, i2 = i + 4 + half, i3 = i + 6 + half;
            int   s0 = __shfl_sync(0xffffffffu, ssrc, i0);
            int   s1 = __shfl_sync(0xffffffffu, ssrc, i1);
            int   s2 = __shfl_sync(0xffffffffu, ssrc, i2);
            int   s3 = __shfl_sync(0xffffffffu, ssrc, i3);
            float c0 = __shfl_sync(0xffffffffu, cl, i0);
            float c1 = __shfl_sync(0xffffffffu, cl, i1);
            float c2 = __shfl_sync(0xffffffffu, cl, i2);
            float c3 = __shfl_sync(0xffffffffu, cl, i3);
            uint4 u0 = *(const uint4*)(z_in + s0 * D + col);
            uint4 u1 = *(const uint4*)(z_in + s1 * D + col);
            uint4 u2 = *(const uint4*)(z_in + s2 * D + col);
            uint4 u3 = *(const uint4*)(z_in + s3 * D + col);
            accp2(acc, c0, u0);
            accp2(acc, c1, u1);
            accp2(acc, c2, u2);
            accp2(acc, c3, u3);
        }
        for (; i < m; i += 2) {                   // tail pairs (lanes >= m have cl = 0)
            int i0 = i + half;
            int   s0 = __shfl_sync(0xffffffffu, ssrc, i0);
            float c0 = __shfl_sync(0xffffffffu, cl, i0);
            uint4 u0 = *(const uint4*)(z_in + s0 * D + col);
            accp2(acc, c0, u0);
        }
    }

    float r[8];
    #pragma unroll
    for (int q = 0; q < 4; q++)
        asm("mov.b64 {%0, %1}, %2;" : "=f"(r[2 * q]), "=f"(r[2 * q + 1]) : "l"(acc[q]));
    #pragma unroll
    for (int j = 0; j < 8; j++)
        r[j] += __shfl_xor_sync(0xffffffffu, r[j], 16);

    if (half == 0) {
        float2 av = ab[gw];
        uint4 fu = *(const uint4*)(g_f016 + gw * D + col);
        __half2* fp = (__half2*)&fu;
        uint4 ou;
        unsigned int* op = (unsigned int*)&ou;
        #pragma unroll
        for (int q = 0; q < 4; q++) {
            float2 f = __half22float2(fp[q]);
            __half2 o = __floats2half2_rn(fmaf(av.x, r[2 * q],     av.y * f.x),
                                          fmaf(av.x, r[2 * q + 1], av.y * f.y));
            op[q] = *(unsigned int*)&o;
        }
        *(uint4*)(h_out + gw * D + col) = ou;
    }
}

// ---------------- output MLP via wmma HMMA: gelu(x@W1+b1)@W2+b2 ----------------
#define MROWS 64
#define LDH 136   // halves (= floats) leading dim, padded

__global__ void __launch_bounds__(256) k_mlp(const __half* __restrict__ x,
                                             const __half* __restrict__ W1h,
                                             const float* __restrict__ b1,
                                             const __half* __restrict__ W2h,
                                             const float* __restrict__ b2,
                                             float* __restrict__ out) {
    extern __shared__ __half smh[];
    __half* Ws = smh;                         // 128 x LDH halves
    __half* xs = smh + 128 * LDH;             // 64 x LDH halves
    float*  fs = (float*)(xs + MROWS * LDH);  // 64 x LDH floats
    int tid = threadIdx.x, w = tid >> 5;
    int row0 = blockIdx.x * MROWS;
    int rw = w & 3, ch = w >> 2;

    for (int i = tid; i < 128 * 128; i += 256)
        Ws[(i >> 7) * LDH + (i & 127)] = W1h[i];
    for (int i = tid; i < MROWS * 16; i += 256) {     // uint4 = 8 halves
        int r = i >> 4, c8 = i & 15, gr = row0 + r;
        uint4 v = make_uint4(0u, 0u, 0u, 0u);
        if (gr < N_NODES) v = *(const uint4*)(x + gr * D + c8 * 8);
        *(uint4*)(xs + r * LDH + c8 * 8) = v;
    }
    __syncthreads();

    wmma::fragment<wmma::accumulator, 16, 16, 16, float> acc[4];
    #pragma unroll
    for (int j = 0; j < 4; j++) wmma::fill_fragment(acc[j], 0.0f);
    #pragma unroll
    for (int k0 = 0; k0 < 128; k0 += 16) {
        wmma::fragment<wmma::matrix_a, 16, 16, 16, __half, wmma::row_major> af;
        wmma::load_matrix_sync(af, xs + rw * 16 * LDH + k0, LDH);
        #pragma unroll
        for (int j = 0; j < 4; j++) {
            wmma::fragment<wmma::matrix_b, 16, 16, 16, __half, wmma::row_major> bf;
            wmma::load_matrix_sync(bf, Ws + k0 * LDH + ch * 64 + j * 16, LDH);
            wmma::mma_sync(acc[j], af, bf, acc[j]);
        }
    }
    #pragma unroll
    for (int j = 0; j < 4; j++)
        wmma::store_matrix_sync(fs + rw * 16 * LDH + ch * 64 + j * 16, acc[j], LDH,
                                wmma::mem_row_major);
    __syncthreads();

    for (int i = tid; i < MROWS * 128; i += 256) {
        int r = i >> 7, c = i & 127;
        xs[r * LDH + c] = __float2half_rn(gelu_exact(fs[r * LDH + c] + b1[c]));
    }
    for (int i = tid; i < 128 * 128; i += 256)
        Ws[(i >> 7) * LDH + (i & 127)] = W2h[i];
    __syncthreads();

    #pragma unroll
    for (int j = 0; j < 4; j++) wmma::fill_fragment(acc[j], 0.0f);
    #pragma unroll
    for (int k0 = 0; k0 < 128; k0 += 16) {
        wmma::fragment<wmma::matrix_a, 16, 16, 16, __half, wmma::row_major> af;
        wmma::load_matrix_sync(af, xs + rw * 16 * LDH + k0, LDH);
        #pragma unroll
        for (int j = 0; j < 4; j++) {
            wmma::fragment<wmma::matrix_b, 16, 16, 16, __half, wmma::row_major> bf;
            wmma::load_matrix_sync(bf, Ws + k0 * LDH + ch * 64 + j * 16, LDH);
            wmma::mma_sync(acc[j], af, bf, acc[j]);
        }
    }
    #pragma unroll
    for (int j = 0; j < 4; j++)
        wmma::store_matrix_sync(fs + rw * 16 * LDH + ch * 64 + j * 16, acc[j], LDH,
                                wmma::mem_row_major);
    __syncthreads();

    for (int i = tid; i < MROWS * 128; i += 256) {
        int r = i >> 7, c = i & 127, gr = row0 + r;
        if (gr < N_NODES) out[gr * D + c] = fs[r * LDH + c] + b2[c];
    }
}

// ---------------- launch ----------------
extern "C" void kernel_launch(void* const* d_in, const int* in_sizes, int n_in,
                              void* d_out, int out_size) {
    const float* feat  = (const float*)d_in[0];
    const int*   e_ft  = (const int*)  d_in[1];
    const int*   src   = (const int*)  d_in[2];
    const int*   dst   = (const int*)  d_in[3];
    const float* emb   = (const float*)d_in[4];
    const float* We1   = (const float*)d_in[5];
    const float* be1   = (const float*)d_in[6];
    const float* We2   = (const float*)d_in[7];
    const float* be2   = (const float*)d_in[8];
    const float* W1    = (const float*)d_in[9];
    const float* b1    = (const float*)d_in[10];
    const float* W2    = (const float*)d_in[11];
    const float* b2    = (const float*)d_in[12];
    float* out = (float*)d_out;

    k_zero<<<(N_NODES + 255) / 256, 256>>>();                           // 0
    k_deg<<<(N_EDGES + 255) / 256, 256>>>(src, dst);                    // 1
    k_scan<<<1, 1024>>>();                                              // 2 (+norms+order)
    k_scatter<<<(N_EDGES + 255) / 256, 256>>>(src, dst, e_ft);          // 3  <- profiled
    k_cvtgate<<<CB + 129, 256>>>(feat, W1, W2, emb, We1, be1, We2, be2);// 4

    __half *hA = nullptr, *hB = nullptr, *w1h = nullptr, *w2h = nullptr;
    float2 *abZ = nullptr, *abH = nullptr;
    cudaGetSymbolAddress((void**)&hA, g_h16A);
    cudaGetSymbolAddress((void**)&hB, g_h16B);
    cudaGetSymbolAddress((void**)&abZ, g_abZ);
    cudaGetSymbolAddress((void**)&abH, g_abH);
    cudaGetSymbolAddress((void**)&w1h, g_W1h);
    cudaGetSymbolAddress((void**)&w2h, g_W2h);

    const __half* zin = hA;       // z0 in buffer A
    __half* hout = hB;
    int hop_blocks = (N_NODES * 32 + 255) / 256;
    for (int k = 0; k < K_HOPS; k++) {
        const float2* ab = (k == K_HOPS - 1) ? abH : abZ;
        k_hop<<<hop_blocks, 256>>>(zin, hout, ab);
        zin  = hout;
        hout = (hout == hA) ? hB : hA;
    }

    size_t smem_bytes = (size_t)(128 * LDH + MROWS * LDH) * sizeof(__half)
                      + (size_t)(MROWS * LDH) * sizeof(float);
    cudaFuncSetAttribute(k_mlp, cudaFuncAttributeMaxDynamicSharedMemorySize, (int)smem_bytes);
    k_mlp<<<(N_NODES + MROWS - 1) / MROWS, 256, smem_bytes>>>(zin, w1h, b1, w2h, b2, out);
}

// round 15
// speedup vs baseline: 1.0619x; 1.0619x over previous
#include <cuda_runtime.h>
#include <cuda_fp16.h>
#include <mma.h>
#include <math.h>

using namespace nvcuda;

#define N_NODES 50000
#define N_EDGES 1600000
#define D 128
#define NET 8
#define K_HOPS 10

#define CB ((N_NODES * D / 4 + 255) / 256)  // cvt blocks

// ---- static scratch ----
__device__ __half g_h16A[N_NODES * D];
__device__ __half g_h16B[N_NODES * D];
__device__ __half g_f016[N_NODES * D];   // fp16(feat) for residual
__device__ int   g_meta[N_EDGES + 64];   // src | (etype<<16), CSR-ordered by dst
__device__ int   g_ptr[N_NODES + 1];
__device__ int   g_indeg[N_NODES];
__device__ int   g_outdeg[N_NODES];
__device__ int   g_fill[N_NODES];
__device__ float g_srcnorm[N_NODES];
__device__ float2 g_abZ[N_NODES];        // {0.9*dn*sn, 0.1*sn}  -> writes z = h*sn
__device__ float2 g_abH[N_NODES];        // {0.9*dn,    0.1   }  -> writes h (last hop)
__device__ float g_gate[NET];            // 1 + sigmoid(MLP(embed[t]))
__device__ __half g_W1h[D * D];          // fp16 copies of MLP weights
__device__ __half g_W2h[D * D];

__device__ __forceinline__ float gelu_exact(float x) {
    return 0.5f * x * (1.0f + erff(x * 0.70710678118654752440f));
}

// ---------------- launch 0: zero counters ----------------
__global__ void k_zero() {
    int i = blockIdx.x * blockDim.x + threadIdx.x;
    if (i < N_NODES) { g_indeg[i] = 0; g_outdeg[i] = 0; g_fill[i] = 0; }
}

// ---------------- launch 1: degree count ----------------
__global__ void k_deg(const int* __restrict__ src, const int* __restrict__ dst) {
    int e = blockIdx.x * blockDim.x + threadIdx.x;
    if (e < N_EDGES) {
        atomicAdd(&g_outdeg[src[e]], 1);
        atomicAdd(&g_indeg[dst[e]], 1);
    }
}

// ---------------- launch 2: prefix scan of indeg -> CSR ptr, + norms fused ----------
__global__ void k_scan() {
    __shared__ int sm[1024];
    int t = threadIdx.x;
    const int CH = (N_NODES + 1023) / 1024;   // 49
    int beg = t * CH, end = min(beg + CH, N_NODES);
    int s = 0;
    for (int i = beg; i < end; i++) {
        int id = g_indeg[i];
        s += id;
        float sn = rsqrtf(fmaxf((float)g_outdeg[i], 1.0f));
        float dn = rsqrtf(fmaxf((float)id, 1.0f));
        g_srcnorm[i] = sn;
        g_abZ[i] = make_float2(0.9f * dn * sn, 0.1f * sn);
        g_abH[i] = make_float2(0.9f * dn, 0.1f);
    }
    sm[t] = s;
    __syncthreads();
    for (int d = 1; d < 1024; d <<= 1) {
        int add = (t >= d) ? sm[t - d] : 0;
        __syncthreads();
        sm[t] += add;
        __syncthreads();
    }
    int off = sm[t] - s;
    for (int i = beg; i < end; i++) { g_ptr[i] = off; off += g_indeg[i]; }
    if (t == 1023) g_ptr[N_NODES] = off;
}

// ---------------- launch 3 (PROFILED SLOT): bucket edges by dst ----------------
__global__ void k_scatter(const int* __restrict__ src, const int* __restrict__ dst,
                          const int* __restrict__ ef) {
    int e = blockIdx.x * blockDim.x + threadIdx.x;
    if (e < N_EDGES) {
        int d = dst[e];
        int pos = g_ptr[d] + atomicAdd(&g_fill[d], 1);
        g_meta[pos] = src[e] | (ef[e] << 16);   // src < 65536, etype < 8
    }
}

// ------- launch 4: z0/f016 converts + W1/W2 -> fp16 + edge gate, one fused grid -------
__global__ void k_cvtgate(const float* __restrict__ feat,
                          const float* __restrict__ W1, const float* __restrict__ W2,
                          const float* __restrict__ emb, const float* __restrict__ We1,
                          const float* __restrict__ be1, const float* __restrict__ We2,
                          const float* __restrict__ be2) {
    int b = blockIdx.x, tid = threadIdx.x;
    if (b < CB) {
        int i = b * 256 + tid;
        if (i < N_NODES * D / 4) {
            int row = i >> 5;                       // (i*4)/128
            float sn = g_srcnorm[row];
            float4 v = *(const float4*)(feat + i * 4);
            __half2 a = __floats2half2_rn(v.x, v.y);
            __half2 c = __floats2half2_rn(v.z, v.w);
            uint2 u;  u.x = *(unsigned int*)&a;  u.y = *(unsigned int*)&c;
            *(uint2*)(g_f016 + i * 4) = u;
            __half2 za = __floats2half2_rn(v.x * sn, v.y * sn);
            __half2 zc = __floats2half2_rn(v.z * sn, v.w * sn);
            uint2 zu; zu.x = *(unsigned int*)&za; zu.y = *(unsigned int*)&zc;
            *(uint2*)(g_h16A + i * 4) = zu;         // z0 lives in buffer A
        }
    } else if (b < CB + 64) {
        int i = (b - CB) * 256 + tid;               // 64*256 = 16384 = D*D
        g_W1h[i] = __float2half_rn(W1[i]);
    } else if (b < CB + 128) {
        int i = (b - CB - 64) * 256 + tid;
        g_W2h[i] = __float2half_rn(W2[i]);
    } else {
        int w = tid >> 5, lane = tid & 31;
        if (w < NET) {
            float acc = be1[lane];
            #pragma unroll 8
            for (int i = 0; i < D; i++)
                acc = fmaf(emb[w * D + i], We1[i * 32 + lane], acc);
            float g = gelu_exact(acc);
            float v = g * We2[lane];
            #pragma unroll
            for (int o = 16; o; o >>= 1) v += __shfl_down_sync(0xffffffffu, v, o);
            if (lane == 0)
                g_gate[w] = 1.0f + 1.0f / (1.0f + expf(-(v + be2[0])));
        }
    }
}

// ---------------- hop: warp per dst node, 2 edges/LDG.128, packed f32x2 FMA ------------
// 128-thread blocks: same warp-level code, finer scheduling quantum (smaller tails).
__device__ __forceinline__ void accp2(unsigned long long* a, float cbc, uint4 u) {
    unsigned long long c2;
    asm("mov.b64 %0, {%1, %1};" : "=l"(c2) : "f"(cbc));
    __half2* hp = (__half2*)&u;
    #pragma unroll
    for (int q = 0; q < 4; q++) {
        float2 f = __half22float2(hp[q]);
        unsigned long long v;
        asm("mov.b64 %0, {%1, %2};" : "=l"(v) : "f"(f.x), "f"(f.y));
        asm("fma.rn.f32x2 %0, %1, %2, %0;" : "+l"(a[q]) : "l"(v), "l"(c2));
    }
}

__global__ void __launch_bounds__(128, 10) k_hop(const __half* __restrict__ z_in,
                                                 __half* __restrict__ h_out,
                                                 const float2* __restrict__ ab) {
    int gw   = (blockIdx.x * blockDim.x + threadIdx.x) >> 5;  // node id
    int lane = threadIdx.x & 31;
    if (gw >= N_NODES) return;
    int beg = g_ptr[gw], end = g_ptr[gw + 1];
    int half = lane >> 4;
    int col  = (lane & 15) * 8;                   // 8 halves (16 B) per lane
    float gate_reg = g_gate[lane & 7];            // 8 gate values resident in warp

    unsigned long long acc[4] = {0ull, 0ull, 0ull, 0ull};

    for (int e0 = beg; e0 < end; e0 += 32) {
        int m = min(32, end - e0);
        int mv = (lane < m) ? g_meta[e0 + lane] : 0;
        int ssrc = mv & 0xffff;
        float gv = __shfl_sync(0xffffffffu, gate_reg, (mv >> 16) & 7);
        float cl = (lane < m) ? gv : 0.0f;        // inactive lanes contribute 0
        int i = 0;
        for (; i + 8 <= m; i += 8) {              // 4 pairs = 8 edges, 4 LDG.128 in flight
            int i0 = i + half, i1 = i + 2 + half, i2 = i + 4 + half, i3 = i + 6 + half;
            int   s0 = __shfl_sync(0xffffffffu, ssrc, i0);
            int   s1 = __shfl_sync(0xffffffffu, ssrc, i1);
            int   s2 = __shfl_sync(0xffffffffu, ssrc, i2);
            int   s3 = __shfl_sync(0xffffffffu, ssrc, i3);
            float c0 = __shfl_sync(0xffffffffu, cl, i0);
            float c1 = __shfl_sync(0xffffffffu, cl, i1);
            float c2 = __shfl_sync(0xffffffffu, cl, i2);
            float c3 = __shfl_sync(0xffffffffu, cl, i3);
            uint4 u0 = *(const uint4*)(z_in + s0 * D + col);
            uint4 u1 = *(const uint4*)(z_in + s1 * D + col);
            uint4 u2 = *(const uint4*)(z_in + s2 * D + col);
            uint4 u3 = *(const uint4*)(z_in + s3 * D + col);
            accp2(acc, c0, u0);
            accp2(acc, c1, u1);
            accp2(acc, c2, u2);
            accp2(acc, c3, u3);
        }
        for (; i < m; i += 2) {                   // tail pairs (lanes >= m have cl = 0)
            int i0 = i + half;
            int   s0 = __shfl_sync(0xffffffffu, ssrc, i0);
            float c0 = __shfl_sync(0xffffffffu, cl, i0);
            uint4 u0 = *(const uint4*)(z_in + s0 * D + col);
            accp2(acc, c0, u0);
        }
    }

    float r[8];
    #pragma unroll
    for (int q = 0; q < 4; q++)
        asm("mov.b64 {%0, %1}, %2;" : "=f"(r[2 * q]), "=f"(r[2 * q + 1]) : "l"(acc[q]));
    #pragma unroll
    for (int j = 0; j < 8; j++)
        r[j] += __shfl_xor_sync(0xffffffffu, r[j], 16);

    if (half == 0) {
        float2 av = ab[gw];
        uint4 fu = *(const uint4*)(g_f016 + gw * D + col);
        __half2* fp = (__half2*)&fu;
        uint4 ou;
        unsigned int* op = (unsigned int*)&ou;
        #pragma unroll
        for (int q = 0; q < 4; q++) {
            float2 f = __half22float2(fp[q]);
            __half2 o = __floats2half2_rn(fmaf(av.x, r[2 * q],     av.y * f.x),
                                          fmaf(av.x, r[2 * q + 1], av.y * f.y));
            op[q] = *(unsigned int*)&o;
        }
        *(uint4*)(h_out + gw * D + col) = ou;
    }
}

// ---------------- output MLP via wmma HMMA: gelu(x@W1+b1)@W2+b2 ----------------
#define MROWS 64
#define LDH 136   // halves (= floats) leading dim, padded

__global__ void __launch_bounds__(256) k_mlp(const __half* __restrict__ x,
                                             const __half* __restrict__ W1h,
                                             const float* __restrict__ b1,
                                             const __half* __restrict__ W2h,
                                             const float* __restrict__ b2,
                                             float* __restrict__ out) {
    extern __shared__ __half smh[];
    __half* Ws = smh;                         // 128 x LDH halves
    __half* xs = smh + 128 * LDH;             // 64 x LDH halves
    float*  fs = (float*)(xs + MROWS * LDH);  // 64 x LDH floats
    int tid = threadIdx.x, w = tid >> 5;
    int row0 = blockIdx.x * MROWS;
    int rw = w & 3, ch = w >> 2;

    for (int i = tid; i < 128 * 128; i += 256)
        Ws[(i >> 7) * LDH + (i & 127)] = W1h[i];
    for (int i = tid; i < MROWS * 16; i += 256) {     // uint4 = 8 halves
        int r = i >> 4, c8 = i & 15, gr = row0 + r;
        uint4 v = make_uint4(0u, 0u, 0u, 0u);
        if (gr < N_NODES) v = *(const uint4*)(x + gr * D + c8 * 8);
        *(uint4*)(xs + r * LDH + c8 * 8) = v;
    }
    __syncthreads();

    wmma::fragment<wmma::accumulator, 16, 16, 16, float> acc[4];
    #pragma unroll
    for (int j = 0; j < 4; j++) wmma::fill_fragment(acc[j], 0.0f);
    #pragma unroll
    for (int k0 = 0; k0 < 128; k0 += 16) {
        wmma::fragment<wmma::matrix_a, 16, 16, 16, __half, wmma::row_major> af;
        wmma::load_matrix_sync(af, xs + rw * 16 * LDH + k0, LDH);
        #pragma unroll
        for (int j = 0; j < 4; j++) {
            wmma::fragment<wmma::matrix_b, 16, 16, 16, __half, wmma::row_major> bf;
            wmma::load_matrix_sync(bf, Ws + k0 * LDH + ch * 64 + j * 16, LDH);
            wmma::mma_sync(acc[j], af, bf, acc[j]);
        }
    }
    #pragma unroll
    for (int j = 0; j < 4; j++)
        wmma::store_matrix_sync(fs + rw * 16 * LDH + ch * 64 + j * 16, acc[j], LDH,
                                wmma::mem_row_major);
    __syncthreads();

    for (int i = tid; i < MROWS * 128; i += 256) {
        int r = i >> 7, c = i & 127;
        xs[r * LDH + c] = __float2half_rn(gelu_exact(fs[r * LDH + c] + b1[c]));
    }
    for (int i = tid; i < 128 * 128; i += 256)
        Ws[(i >> 7) * LDH + (i & 127)] = W2h[i];
    __syncthreads();

    #pragma unroll
    for (int j = 0; j < 4; j++) wmma::fill_fragment(acc[j], 0.0f);
    #pragma unroll
    for (int k0 = 0; k0 < 128; k0 += 16) {
        wmma::fragment<wmma::matrix_a, 16, 16, 16, __half, wmma::row_major> af;
        wmma::load_matrix_sync(af, xs + rw * 16 * LDH + k0, LDH);
        #pragma unroll
        for (int j = 0; j < 4; j++) {
            wmma::fragment<wmma::matrix_b, 16, 16, 16, __half, wmma::row_major> bf;
            wmma::load_matrix_sync(bf, Ws + k0 * LDH + ch * 64 + j * 16, LDH);
            wmma::mma_sync(acc[j], af, bf, acc[j]);
        }
    }
    #pragma unroll
    for (int j = 0; j < 4; j++)
        wmma::store_matrix_sync(fs + rw * 16 * LDH + ch * 64 + j * 16, acc[j], LDH,
                                wmma::mem_row_major);
    __syncthreads();

    for (int i = tid; i < MROWS * 128; i += 256) {
        int r = i >> 7, c = i & 127, gr = row0 + r;
        if (gr < N_NODES) out[gr * D + c] = fs[r * LDH + c] + b2[c];
    }
}

// ---------------- launch ----------------
extern "C" void kernel_launch(void* const* d_in, const int* in_sizes, int n_in,
                              void* d_out, int out_size) {
    const float* feat  = (const float*)d_in[0];
    const int*   e_ft  = (const int*)  d_in[1];
    const int*   src   = (const int*)  d_in[2];
    const int*   dst   = (const int*)  d_in[3];
    const float* emb   = (const float*)d_in[4];
    const float* We1   = (const float*)d_in[5];
    const float* be1   = (const float*)d_in[6];
    const float* We2   = (const float*)d_in[7];
    const float* be2   = (const float*)d_in[8];
    const float* W1    = (const float*)d_in[9];
    const float* b1    = (const float*)d_in[10];
    const float* W2    = (const float*)d_in[11];
    const float* b2    = (const float*)d_in[12];
    float* out = (float*)d_out;

    k_zero<<<(N_NODES + 255) / 256, 256>>>();                           // 0
    k_deg<<<(N_EDGES + 255) / 256, 256>>>(src, dst);                    // 1
    k_scan<<<1, 1024>>>();                                              // 2 (+norms)
    k_scatter<<<(N_EDGES + 255) / 256, 256>>>(src, dst, e_ft);          // 3  <- profiled
    k_cvtgate<<<CB + 129, 256>>>(feat, W1, W2, emb, We1, be1, We2, be2);// 4

    __half *hA = nullptr, *hB = nullptr, *w1h = nullptr, *w2h = nullptr;
    float2 *abZ = nullptr, *abH = nullptr;
    cudaGetSymbolAddress((void**)&hA, g_h16A);
    cudaGetSymbolAddress((void**)&hB, g_h16B);
    cudaGetSymbolAddress((void**)&abZ, g_abZ);
    cudaGetSymbolAddress((void**)&abH, g_abH);
    cudaGetSymbolAddress((void**)&w1h, g_W1h);
    cudaGetSymbolAddress((void**)&w2h, g_W2h);

    const __half* zin = hA;       // z0 in buffer A
    __half* hout = hB;
    int hop_blocks = (N_NODES * 32 + 127) / 128;   // warp per node, 128-thread blocks
    for (int k = 0; k < K_HOPS; k++) {
        const float2* ab = (k == K_HOPS - 1) ? abH : abZ;
        k_hop<<<hop_blocks, 128>>>(zin, hout, ab);
        zin  = hout;
        hout = (hout == hA) ? hB : hA;
    }

    size_t smem_bytes = (size_t)(128 * LDH + MROWS * LDH) * sizeof(__half)
                      + (size_t)(MROWS * LDH) * sizeof(float);
    cudaFuncSetAttribute(k_mlp, cudaFuncAttributeMaxDynamicSharedMemorySize, (int)smem_bytes);
    k_mlp<<<(N_NODES + MROWS - 1) / MROWS, 256, smem_bytes>>>(zin, w1h, b1, w2h, b2, out);
}

// round 16
// speedup vs baseline: 1.0641x; 1.0021x over previous
#include <cuda_runtime.h>
#include <cuda_fp16.h>
#include <mma.h>
#include <math.h>

using namespace nvcuda;

#define N_NODES 50000
#define N_EDGES 1600000
#define D 128
#define NET 8
#define K_HOPS 10

#define CB ((N_NODES * D / 4 + 255) / 256)  // cvt blocks

// ---- static scratch ----
__device__ __half g_h16A[N_NODES * D];
__device__ __half g_h16B[N_NODES * D];
__device__ __half g_f016[N_NODES * D];   // fp16(feat) for residual
__device__ int   g_meta[N_EDGES + 64];   // src | (etype<<16), CSR-ordered by dst
__device__ int   g_ptr[N_NODES + 1];
__device__ int   g_indeg[N_NODES];
__device__ int   g_outdeg[N_NODES];
__device__ int   g_fill[N_NODES];
__device__ float g_srcnorm[N_NODES];
__device__ float2 g_abZ[N_NODES];        // {0.9*dn*sn, 0.1*sn}  -> writes z = h*sn
__device__ float2 g_abH[N_NODES];        // {0.9*dn,    0.1   }  -> writes h (last hop)
__device__ float g_gate[NET];            // 1 + sigmoid(MLP(embed[t]))
__device__ __half g_W1h[D * D];          // fp16 copies of MLP weights
__device__ __half g_W2h[D * D];

__device__ __forceinline__ float gelu_exact(float x) {
    return 0.5f * x * (1.0f + erff(x * 0.70710678118654752440f));
}

// ---------------- launch 0: zero counters ----------------
__global__ void k_zero() {
    int i = blockIdx.x * blockDim.x + threadIdx.x;
    if (i < N_NODES) { g_indeg[i] = 0; g_outdeg[i] = 0; g_fill[i] = 0; }
}

// ---------------- launch 1: degree count ----------------
__global__ void k_deg(const int* __restrict__ src, const int* __restrict__ dst) {
    int e = blockIdx.x * blockDim.x + threadIdx.x;
    if (e < N_EDGES) {
        atomicAdd(&g_outdeg[src[e]], 1);
        atomicAdd(&g_indeg[dst[e]], 1);
    }
}

// ---------------- launch 2: prefix scan of indeg -> CSR ptr, + norms fused ----------
__global__ void k_scan() {
    __shared__ int sm[1024];
    int t = threadIdx.x;
    const int CH = (N_NODES + 1023) / 1024;   // 49
    int beg = t * CH, end = min(beg + CH, N_NODES);
    int s = 0;
    for (int i = beg; i < end; i++) {
        int id = g_indeg[i];
        s += id;
        float sn = rsqrtf(fmaxf((float)g_outdeg[i], 1.0f));
        float dn = rsqrtf(fmaxf((float)id, 1.0f));
        g_srcnorm[i] = sn;
        g_abZ[i] = make_float2(0.9f * dn * sn, 0.1f * sn);
        g_abH[i] = make_float2(0.9f * dn, 0.1f);
    }
    sm[t] = s;
    __syncthreads();
    for (int d = 1; d < 1024; d <<= 1) {
        int add = (t >= d) ? sm[t - d] : 0;
        __syncthreads();
        sm[t] += add;
        __syncthreads();
    }
    int off = sm[t] - s;
    for (int i = beg; i < end; i++) { g_ptr[i] = off; off += g_indeg[i]; }
    if (t == 1023) g_ptr[N_NODES] = off;
}

// ---------------- launch 3 (PROFILED SLOT): bucket edges by dst ----------------
__global__ void k_scatter(const int* __restrict__ src, const int* __restrict__ dst,
                          const int* __restrict__ ef) {
    int e = blockIdx.x * blockDim.x + threadIdx.x;
    if (e < N_EDGES) {
        int d = dst[e];
        int pos = g_ptr[d] + atomicAdd(&g_fill[d], 1);
        g_meta[pos] = src[e] | (ef[e] << 16);   // src < 65536, etype < 8
    }
}

// ------- launch 4: z0/f016 converts + W1/W2 -> fp16 + edge gate, one fused grid -------
__global__ void k_cvtgate(const float* __restrict__ feat,
                          const float* __restrict__ W1, const float* __restrict__ W2,
                          const float* __restrict__ emb, const float* __restrict__ We1,
                          const float* __restrict__ be1, const float* __restrict__ We2,
                          const float* __restrict__ be2) {
    int b = blockIdx.x, tid = threadIdx.x;
    if (b < CB) {
        int i = b * 256 + tid;
        if (i < N_NODES * D / 4) {
            int row = i >> 5;                       // (i*4)/128
            float sn = g_srcnorm[row];
            float4 v = *(const float4*)(feat + i * 4);
            __half2 a = __floats2half2_rn(v.x, v.y);
            __half2 c = __floats2half2_rn(v.z, v.w);
            uint2 u;  u.x = *(unsigned int*)&a;  u.y = *(unsigned int*)&c;
            *(uint2*)(g_f016 + i * 4) = u;
            __half2 za = __floats2half2_rn(v.x * sn, v.y * sn);
            __half2 zc = __floats2half2_rn(v.z * sn, v.w * sn);
            uint2 zu; zu.x = *(unsigned int*)&za; zu.y = *(unsigned int*)&zc;
            *(uint2*)(g_h16A + i * 4) = zu;         // z0 lives in buffer A
        }
    } else if (b < CB + 64) {
        int i = (b - CB) * 256 + tid;               // 64*256 = 16384 = D*D
        g_W1h[i] = __float2half_rn(W1[i]);
    } else if (b < CB + 128) {
        int i = (b - CB - 64) * 256 + tid;
        g_W2h[i] = __float2half_rn(W2[i]);
    } else {
        int w = tid >> 5, lane = tid & 31;
        if (w < NET) {
            float acc = be1[lane];
            #pragma unroll 8
            for (int i = 0; i < D; i++)
                acc = fmaf(emb[w * D + i], We1[i * 32 + lane], acc);
            float g = gelu_exact(acc);
            float v = g * We2[lane];
            #pragma unroll
            for (int o = 16; o; o >>= 1) v += __shfl_down_sync(0xffffffffu, v, o);
            if (lane == 0)
                g_gate[w] = 1.0f + 1.0f / (1.0f + expf(-(v + be2[0])));
        }
    }
}

// ---------------- hop: warp per dst node, 2 edges/LDG.128, packed f32x2 FMA ------------
// 64-thread blocks: same warp-level code, finest scheduling quantum (smallest tails).
__device__ __forceinline__ void accp2(unsigned long long* a, float cbc, uint4 u) {
    unsigned long long c2;
    asm("mov.b64 %0, {%1, %1};" : "=l"(c2) : "f"(cbc));
    __half2* hp = (__half2*)&u;
    #pragma unroll
    for (int q = 0; q < 4; q++) {
        float2 f = __half22float2(hp[q]);
        unsigned long long v;
        asm("mov.b64 %0, {%1, %2};" : "=l"(v) : "f"(f.x), "f"(f.y));
        asm("fma.rn.f32x2 %0, %1, %2, %0;" : "+l"(a[q]) : "l"(v), "l"(c2));
    }
}

__global__ void __launch_bounds__(64, 20) k_hop(const __half* __restrict__ z_in,
                                                __half* __restrict__ h_out,
                                                const float2* __restrict__ ab) {
    int gw   = (blockIdx.x * blockDim.x + threadIdx.x) >> 5;  // node id
    int lane = threadIdx.x & 31;
    if (gw >= N_NODES) return;
    int beg = g_ptr[gw], end = g_ptr[gw + 1];
    int half = lane >> 4;
    int col  = (lane & 15) * 8;                   // 8 halves (16 B) per lane
    float gate_reg = g_gate[lane & 7];            // 8 gate values resident in warp

    unsigned long long acc[4] = {0ull, 0ull, 0ull, 0ull};

    for (int e0 = beg; e0 < end; e0 += 32) {
        int m = min(32, end - e0);
        int mv = (lane < m) ? g_meta[e0 + lane] : 0;
        int ssrc = mv & 0xffff;
        float gv = __shfl_sync(0xffffffffu, gate_reg, (mv >> 16) & 7);
        float cl = (lane < m) ? gv : 0.0f;        // inactive lanes contribute 0
        int i = 0;
        for (; i + 8 <= m; i += 8) {              // 4 pairs = 8 edges, 4 LDG.128 in flight
            int i0 = i + half, i1 = i + 2 + half, i2 = i + 4 + half, i3 = i + 6 + half;
            int   s0 = __shfl_sync(0xffffffffu, ssrc, i0);
            int   s1 = __shfl_sync(0xffffffffu, ssrc, i1);
            int   s2 = __shfl_sync(0xffffffffu, ssrc, i2);
            int   s3 = __shfl_sync(0xffffffffu, ssrc, i3);
            float c0 = __shfl_sync(0xffffffffu, cl, i0);
            float c1 = __shfl_sync(0xffffffffu, cl, i1);
            float c2 = __shfl_sync(0xffffffffu, cl, i2);
            float c3 = __shfl_sync(0xffffffffu, cl, i3);
            uint4 u0 = *(const uint4*)(z_in + s0 * D + col);
            uint4 u1 = *(const uint4*)(z_in + s1 * D + col);
            uint4 u2 = *(const uint4*)(z_in + s2 * D + col);
            uint4 u3 = *(const uint4*)(z_in + s3 * D + col);
            accp2(acc, c0, u0);
            accp2(acc, c1, u1);
            accp2(acc, c2, u2);
            accp2(acc, c3, u3);
        }
        for (; i < m; i += 2) {                   // tail pairs (lanes >= m have cl = 0)
            int i0 = i + half;
            int   s0 = __shfl_sync(0xffffffffu, ssrc, i0);
            float c0 = __shfl_sync(0xffffffffu, cl, i0);
            uint4 u0 = *(const uint4*)(z_in + s0 * D + col);
            accp2(acc, c0, u0);
        }
    }

    float r[8];
    #pragma unroll
    for (int q = 0; q < 4; q++)
        asm("mov.b64 {%0, %1}, %2;" : "=f"(r[2 * q]), "=f"(r[2 * q + 1]) : "l"(acc[q]));
    #pragma unroll
    for (int j = 0; j < 8; j++)
        r[j] += __shfl_xor_sync(0xffffffffu, r[j], 16);

    if (half == 0) {
        float2 av = ab[gw];
        uint4 fu = *(const uint4*)(g_f016 + gw * D + col);
        __half2* fp = (__half2*)&fu;
        uint4 ou;
        unsigned int* op = (unsigned int*)&ou;
        #pragma unroll
        for (int q = 0; q < 4; q++) {
            float2 f = __half22float2(fp[q]);
            __half2 o = __floats2half2_rn(fmaf(av.x, r[2 * q],     av.y * f.x),
                                          fmaf(av.x, r[2 * q + 1], av.y * f.y));
            op[q] = *(unsigned int*)&o;
        }
        *(uint4*)(h_out + gw * D + col) = ou;
    }
}

// ---------------- output MLP via wmma HMMA: gelu(x@W1+b1)@W2+b2 ----------------
#define MROWS 64
#define LDH 136   // halves (= floats) leading dim, padded

__global__ void __launch_bounds__(256) k_mlp(const __half* __restrict__ x,
                                             const __half* __restrict__ W1h,
                                             const float* __restrict__ b1,
                                             const __half* __restrict__ W2h,
                                             const float* __restrict__ b2,
                                             float* __restrict__ out) {
    extern __shared__ __half smh[];
    __half* Ws = smh;                         // 128 x LDH halves
    __half* xs = smh + 128 * LDH;             // 64 x LDH halves
    float*  fs = (float*)(xs + MROWS * LDH);  // 64 x LDH floats
    int tid = threadIdx.x, w = tid >> 5;
    int row0 = blockIdx.x * MROWS;
    int rw = w & 3, ch = w >> 2;

    for (int i = tid; i < 128 * 128; i += 256)
        Ws[(i >> 7) * LDH + (i & 127)] = W1h[i];
    for (int i = tid; i < MROWS * 16; i += 256) {     // uint4 = 8 halves
        int r = i >> 4, c8 = i & 15, gr = row0 + r;
        uint4 v = make_uint4(0u, 0u, 0u, 0u);
        if (gr < N_NODES) v = *(const uint4*)(x + gr * D + c8 * 8);
        *(uint4*)(xs + r * LDH + c8 * 8) = v;
    }
    __syncthreads();

    wmma::fragment<wmma::accumulator, 16, 16, 16, float> acc[4];
    #pragma unroll
    for (int j = 0; j < 4; j++) wmma::fill_fragment(acc[j], 0.0f);
    #pragma unroll
    for (int k0 = 0; k0 < 128; k0 += 16) {
        wmma::fragment<wmma::matrix_a, 16, 16, 16, __half, wmma::row_major> af;
        wmma::load_matrix_sync(af, xs + rw * 16 * LDH + k0, LDH);
        #pragma unroll
        for (int j = 0; j < 4; j++) {
            wmma::fragment<wmma::matrix_b, 16, 16, 16, __half, wmma::row_major> bf;
            wmma::load_matrix_sync(bf, Ws + k0 * LDH + ch * 64 + j * 16, LDH);
            wmma::mma_sync(acc[j], af, bf, acc[j]);
        }
    }
    #pragma unroll
    for (int j = 0; j < 4; j++)
        wmma::store_matrix_sync(fs + rw * 16 * LDH + ch * 64 + j * 16, acc[j], LDH,
                                wmma::mem_row_major);
    __syncthreads();

    for (int i = tid; i < MROWS * 128; i += 256) {
        int r = i >> 7, c = i & 127;
        xs[r * LDH + c] = __float2half_rn(gelu_exact(fs[r * LDH + c] + b1[c]));
    }
    for (int i = tid; i < 128 * 128; i += 256)
        Ws[(i >> 7) * LDH + (i & 127)] = W2h[i];
    __syncthreads();

    #pragma unroll
    for (int j = 0; j < 4; j++) wmma::fill_fragment(acc[j], 0.0f);
    #pragma unroll
    for (int k0 = 0; k0 < 128; k0 += 16) {
        wmma::fragment<wmma::matrix_a, 16, 16, 16, __half, wmma::row_major> af;
        wmma::load_matrix_sync(af, xs + rw * 16 * LDH + k0, LDH);
        #pragma unroll
        for (int j = 0; j < 4; j++) {
            wmma::fragment<wmma::matrix_b, 16, 16, 16, __half, wmma::row_major> bf;
            wmma::load_matrix_sync(bf, Ws + k0 * LDH + ch * 64 + j * 16, LDH);
            wmma::mma_sync(acc[j], af, bf, acc[j]);
        }
    }
    #pragma unroll
    for (int j = 0; j < 4; j++)
        wmma::store_matrix_sync(fs + rw * 16 * LDH + ch * 64 + j * 16, acc[j], LDH,
                                wmma::mem_row_major);
    __syncthreads();

    for (int i = tid; i < MROWS * 128; i += 256) {
        int r = i >> 7, c = i & 127, gr = row0 + r;
        if (gr < N_NODES) out[gr * D + c] = fs[r * LDH + c] + b2[c];
    }
}

// ---------------- launch ----------------
extern "C" void kernel_launch(void* const* d_in, const int* in_sizes, int n_in,
                              void* d_out, int out_size) {
    const float* feat  = (const float*)d_in[0];
    const int*   e_ft  = (const int*)  d_in[1];
    const int*   src   = (const int*)  d_in[2];
    const int*   dst   = (const int*)  d_in[3];
    const float* emb   = (const float*)d_in[4];
    const float* We1   = (const float*)d_in[5];
    const float* be1   = (const float*)d_in[6];
    const float* We2   = (const float*)d_in[7];
    const float* be2   = (const float*)d_in[8];
    const float* W1    = (const float*)d_in[9];
    const float* b1    = (const float*)d_in[10];
    const float* W2    = (const float*)d_in[11];
    const float* b2    = (const float*)d_in[12];
    float* out = (float*)d_out;

    k_zero<<<(N_NODES + 255) / 256, 256>>>();                           // 0
    k_deg<<<(N_EDGES + 255) / 256, 256>>>(src, dst);                    // 1
    k_scan<<<1, 1024>>>();                                              // 2 (+norms)
    k_scatter<<<(N_EDGES + 255) / 256, 256>>>(src, dst, e_ft);          // 3  <- profiled
    k_cvtgate<<<CB + 129, 256>>>(feat, W1, W2, emb, We1, be1, We2, be2);// 4

    __half *hA = nullptr, *hB = nullptr, *w1h = nullptr, *w2h = nullptr;
    float2 *abZ = nullptr, *abH = nullptr;
    cudaGetSymbolAddress((void**)&hA, g_h16A);
    cudaGetSymbolAddress((void**)&hB, g_h16B);
    cudaGetSymbolAddress((void**)&abZ, g_abZ);
    cudaGetSymbolAddress((void**)&abH, g_abH);
    cudaGetSymbolAddress((void**)&w1h, g_W1h);
    cudaGetSymbolAddress((void**)&w2h, g_W2h);

    const __half* zin = hA;       // z0 in buffer A
    __half* hout = hB;
    int hop_blocks = (N_NODES * 32 + 63) / 64;     // warp per node, 64-thread blocks
    for (int k = 0; k < K_HOPS; k++) {
        const float2* ab = (k == K_HOPS - 1) ? abH : abZ;
        k_hop<<<hop_blocks, 64>>>(zin, hout, ab);
        zin  = hout;
        hout = (hout == hA) ? hB : hA;
    }

    size_t smem_bytes = (size_t)(128 * LDH + MROWS * LDH) * sizeof(__half)
                      + (size_t)(MROWS * LDH) * sizeof(float);
    cudaFuncSetAttribute(k_mlp, cudaFuncAttributeMaxDynamicSharedMemorySize, (int)smem_bytes);
    k_mlp<<<(N_NODES + MROWS - 1) / MROWS, 256, smem_bytes>>>(zin, w1h, b1, w2h, b2, out);
}